// round 2
// baseline (speedup 1.0000x reference)
#include <cuda_runtime.h>
#include <cuda_bf16.h>
#include <math.h>

// ---------------------------------------------------------------------------
// MAD_4612794876398: LeNet features on (img ++ train[refs]), then
// x/grad projections, per-ref logits, softmax(-||diff||) weighted combine.
//
// Kernel 1 (lenet_kernel): one block per image (9216 blocks).
//   conv1(3->6,k5)+relu+pool2 and conv2(6->16,k5)+relu+pool2 fully fused in
//   shared memory; 400-float feature vector written to global scratch.
// Kernel 2 (head_kernel): one block per query image (1024 blocks).
//   warp-cooperative dot products for Wg/Wf projections, then the small
//   einsum + softmax combine entirely in shared memory.
// ---------------------------------------------------------------------------

#define FEAT 400
#define MAX_TOT (10240)           // capacity: n + n*S  (actual 1024 + 8192)
#define HID 12
#define NCLS 10
#define SMAX 8

// scratch features for all images (query first, then refs)
__device__ float g_feat[MAX_TOT * FEAT];

// ---------------------------------------------------------------------------
// LeNet feature kernel
// ---------------------------------------------------------------------------
__global__ __launch_bounds__(256)
void lenet_kernel(const float* __restrict__ img,
                  const float* __restrict__ train,
                  const int*   __restrict__ refs,
                  const float* __restrict__ w1, const float* __restrict__ b1,
                  const float* __restrict__ w2, const float* __restrict__ b2,
                  int n_img)
{
    __shared__ float s_img[3][32][32];     // 3072
    __shared__ float s_w1[6][3][25];       // 450
    __shared__ float s_b1[6];
    __shared__ float s_p1[6][14][14];      // 1176
    __shared__ float s_w2[16][6][25];      // 2400
    __shared__ float s_b2[16];

    const int b = blockIdx.x;
    const int t = threadIdx.x;

    // source image pointer (gather for reference images)
    const float* src;
    if (b < n_img) {
        src = img + (size_t)b * 3072;
    } else {
        int r = refs[b - n_img];
        src = train + (size_t)r * 3072;
    }

    // load image (float4 vectorized, 3072 floats = 768 float4)
    {
        const float4* s4 = reinterpret_cast<const float4*>(src);
        float4* d4 = reinterpret_cast<float4*>(&s_img[0][0][0]);
        #pragma unroll
        for (int i = 0; i < 3; i++) {
            int k = t + i * 256;
            d4[k] = s4[k];
        }
    }
    // load weights/biases
    {
        float* w1s = &s_w1[0][0][0];
        for (int i = t; i < 450; i += 256) w1s[i] = w1[i];
        float* w2s = &s_w2[0][0][0];
        for (int i = t; i < 2400; i += 256) w2s[i] = w2[i];
        if (t < 6)  s_b1[t] = b1[t];
        if (t < 16) s_b2[t] = b2[t];
    }
    __syncthreads();

    // ---- conv1 + relu + maxpool(2) : output 6 x 14 x 14 ----
    if (t < 196) {
        const int py = t / 14, px = t % 14;
        const int iy = 2 * py, ix = 2 * px;

        float a0[6], a1[6], a2[6], a3[6];
        #pragma unroll
        for (int oc = 0; oc < 6; oc++) {
            float bb = s_b1[oc];
            a0[oc] = bb; a1[oc] = bb; a2[oc] = bb; a3[oc] = bb;
        }
        #pragma unroll
        for (int ic = 0; ic < 3; ic++) {
            float in[6][6];
            #pragma unroll
            for (int r = 0; r < 6; r++)
                #pragma unroll
                for (int c = 0; c < 6; c++)
                    in[r][c] = s_img[ic][iy + r][ix + c];

            #pragma unroll
            for (int oc = 0; oc < 6; oc++) {
                #pragma unroll
                for (int ky = 0; ky < 5; ky++) {
                    #pragma unroll
                    for (int kx = 0; kx < 5; kx++) {
                        float w = s_w1[oc][ic][ky * 5 + kx];
                        a0[oc] += w * in[ky][kx];
                        a1[oc] += w * in[ky][kx + 1];
                        a2[oc] += w * in[ky + 1][kx];
                        a3[oc] += w * in[ky + 1][kx + 1];
                    }
                }
            }
        }
        #pragma unroll
        for (int oc = 0; oc < 6; oc++) {
            float m = fmaxf(fmaxf(a0[oc], a1[oc]), fmaxf(a2[oc], a3[oc]));
            s_p1[oc][py][px] = fmaxf(m, 0.0f);
        }
    }
    __syncthreads();

    // ---- conv2 + relu + maxpool(2) : output 16 x 5 x 5 = 400 feats ----
    for (int i = t; i < 400; i += 256) {
        const int oc = i / 25;
        const int pos = i % 25;
        const int py = pos / 5, px = pos % 5;
        const int iy = 2 * py, ix = 2 * px;

        float bb = s_b2[oc];
        float a0 = bb, a1 = bb, a2 = bb, a3 = bb;

        #pragma unroll
        for (int ic = 0; ic < 6; ic++) {
            float in[6][6];
            #pragma unroll
            for (int r = 0; r < 6; r++)
                #pragma unroll
                for (int c = 0; c < 6; c++)
                    in[r][c] = s_p1[ic][iy + r][ix + c];

            #pragma unroll
            for (int ky = 0; ky < 5; ky++) {
                #pragma unroll
                for (int kx = 0; kx < 5; kx++) {
                    float w = s_w2[oc][ic][ky * 5 + kx];
                    a0 += w * in[ky][kx];
                    a1 += w * in[ky][kx + 1];
                    a2 += w * in[ky + 1][kx];
                    a3 += w * in[ky + 1][kx + 1];
                }
            }
        }
        float m = fmaxf(fmaxf(a0, a1), fmaxf(a2, a3));
        g_feat[(size_t)b * FEAT + i] = fmaxf(m, 0.0f);
    }
}

// ---------------------------------------------------------------------------
// Head kernel: one block per query image, 128 threads (4 warps)
// ---------------------------------------------------------------------------
__device__ __forceinline__ float warp_dot400(const float* __restrict__ a_smem,
                                             const float* __restrict__ g_row)
{
    const int l = threadIdx.x & 31;
    float acc = 0.0f;
    #pragma unroll
    for (int k = 0; k < 13; k++) {
        int kk = l + k * 32;
        if (kk < FEAT) acc += a_smem[kk] * g_row[kk];
    }
    #pragma unroll
    for (int o = 16; o > 0; o >>= 1)
        acc += __shfl_xor_sync(0xFFFFFFFFu, acc, o);
    return acc;
}

__global__ __launch_bounds__(128)
void head_kernel(const float* __restrict__ mem,
                 const int*   __restrict__ refs,
                 const float* __restrict__ Wf, const float* __restrict__ bf,
                 const float* __restrict__ Wg, const float* __restrict__ bg,
                 const float* __restrict__ Wm, const float* __restrict__ bm,
                 float* __restrict__ out, int n, int S)
{
    __shared__ float s_feat[FEAT];
    __shared__ float s_ref[SMAX][FEAT];
    __shared__ float s_grad[HID * NCLS];   // grad[h*NCLS + c]
    __shared__ float s_x[HID];
    __shared__ float s_rx[SMAX][HID];
    __shared__ float s_diff[SMAX][HID];
    __shared__ float s_norm[SMAX];
    __shared__ float s_logit[SMAX][NCLS];
    __shared__ int   s_refs[SMAX];

    const int nq = blockIdx.x;
    const int t = threadIdx.x;
    const int warp = t >> 5;
    const int nwarp = blockDim.x >> 5;

    if (t < S) s_refs[t] = refs[(size_t)nq * S + t];

    // load query feature
    for (int i = t; i < FEAT; i += blockDim.x)
        s_feat[i] = g_feat[(size_t)nq * FEAT + i];
    __syncthreads();

    // load reference features
    for (int i = t; i < S * FEAT; i += blockDim.x) {
        int s = i / FEAT, k = i % FEAT;
        s_ref[s][k] = g_feat[(size_t)(n + nq * S + s) * FEAT + k];
    }
    __syncthreads();

    // cooperative dot-product tasks:
    //   [0, HG)             : grad rows (Wg)
    //   [HG, HG+HID)        : x rows (Wf on query feat)
    //   [HG+HID, ... )      : rx rows (Wf on each ref feat)
    const int HG = HID * NCLS;                 // 120
    const int ntasks = HG + HID + S * HID;     // 228 for S=8
    for (int d = warp; d < ntasks; d += nwarp) {
        float v;
        if (d < HG) {
            v = warp_dot400(s_feat, Wg + (size_t)d * FEAT) + bg[d];
            if ((t & 31) == 0) s_grad[d] = v;
        } else if (d < HG + HID) {
            int h = d - HG;
            v = warp_dot400(s_feat, Wf + (size_t)h * FEAT) + bf[h];
            if ((t & 31) == 0) s_x[h] = v;
        } else {
            int q = d - HG - HID;
            int s = q / HID, h = q % HID;
            v = warp_dot400(s_ref[s], Wf + (size_t)h * FEAT) + bf[h];
            if ((t & 31) == 0) s_rx[s][h] = v;
        }
    }
    __syncthreads();

    // diff = x - rx
    if (t < S * HID) {
        int s = t / HID, h = t % HID;
        s_diff[s][h] = s_x[h] - s_rx[s][h];
    }
    __syncthreads();

    // norms
    if (t < S) {
        float acc = 0.0f;
        #pragma unroll
        for (int h = 0; h < HID; h++) {
            float d = s_diff[t][h];
            acc += d * d;
        }
        s_norm[t] = sqrtf(acc);
    }
    // logits[s][c] = bm[c] + Wm[c,:]·mem[ref_s] + sum_h diff[s][h]*grad[h][c]
    if (t < S * NCLS) {
        int s = t / NCLS, c = t % NCLS;
        int r = s_refs[s];
        float acc = bm[c];
        #pragma unroll
        for (int j = 0; j < NCLS; j++)
            acc += Wm[c * NCLS + j] * mem[(size_t)r * NCLS + j];
        #pragma unroll
        for (int h = 0; h < HID; h++)
            acc += s_diff[s][h] * s_grad[h * NCLS + c];
        s_logit[s][c] = acc;
    }
    __syncthreads();

    // softmax over -norm, weighted combine
    if (t < NCLS) {
        float mx = -1e30f;
        for (int s = 0; s < S; s++) mx = fmaxf(mx, -s_norm[s]);
        float se = 0.0f;
        for (int s = 0; s < S; s++) se += __expf(-s_norm[s] - mx) == 0.0f
                                          ? 0.0f : expf(-s_norm[s] - mx);
        // (use precise expf for both passes)
        se = 0.0f;
        for (int s = 0; s < S; s++) se += expf(-s_norm[s] - mx);
        float acc = 0.0f;
        for (int s = 0; s < S; s++)
            acc += s_logit[t >= 0 ? s : 0][t] * expf(-s_norm[s] - mx);
        out[(size_t)nq * NCLS + t] = acc / se;
    }
}

// ---------------------------------------------------------------------------
// launcher
// ---------------------------------------------------------------------------
extern "C" void kernel_launch(void* const* d_in, const int* in_sizes, int n_in,
                              void* d_out, int out_size)
{
    const float* img   = (const float*)d_in[0];
    const float* train = (const float*)d_in[1];
    const float* mem   = (const float*)d_in[2];
    const float* w1    = (const float*)d_in[3];
    const float* b1    = (const float*)d_in[4];
    const float* w2    = (const float*)d_in[5];
    const float* b2    = (const float*)d_in[6];
    const float* Wf    = (const float*)d_in[7];
    const float* bf    = (const float*)d_in[8];
    const float* Wg    = (const float*)d_in[9];
    const float* bg    = (const float*)d_in[10];
    const float* Wm    = (const float*)d_in[11];
    const float* bm    = (const float*)d_in[12];
    // d_in[13] = idx : unused by the reference computation
    const int*   refs  = (const int*)d_in[14];

    const int n = in_sizes[0] / (3 * 32 * 32);   // 1024
    const int S = in_sizes[14] / n;              // 8
    const int ntot = n + n * S;                  // 9216
    if (ntot > MAX_TOT || S > SMAX) return;      // capacity guard

    lenet_kernel<<<ntot, 256>>>(img, train, refs, w1, b1, w2, b2, n);
    head_kernel<<<n, 128>>>(mem, refs, Wf, bf, Wg, bg, Wm, bm,
                            (float*)d_out, n, S);
}

// round 3
// speedup vs baseline: 1.8526x; 1.8526x over previous
#include <cuda_runtime.h>
#include <cuda_bf16.h>
#include <math.h>

// ---------------------------------------------------------------------------
// MAD_4612794876398
//  K1 lenet_kernel  : fused conv1+pool / conv2+pool using packed fma.rn.f32x2
//                     (2x fp32 throughput). Ref images additionally get their
//                     Wf projection (12 floats) computed in-kernel; query
//                     images store the 400-float feature vector.
//  K2 head_kernel   : 4 queries per block; Wg/Wf dot products with float4
//                     loads amortized over 4 queries; einsum + softmax fused.
// ---------------------------------------------------------------------------

#define FEAT   400
#define HID    12
#define NCLS   10
#define SMAX   8
#define NQ_MAX 1024
#define NR_MAX (NQ_MAX * SMAX)
#define BDIM   224      // lenet block
#define QPB    4        // head queries per block

__device__ float g_feat[NQ_MAX * FEAT];   // query features
__device__ float g_rx[NR_MAX * HID];      // ref projections (Wf·feat + bf)

typedef unsigned long long ull;

__device__ __forceinline__ ull pack2(float lo, float hi) {
    ull r; asm("mov.b64 %0, {%1, %2};" : "=l"(r) : "f"(lo), "f"(hi)); return r;
}
__device__ __forceinline__ void unpack2(ull v, float& lo, float& hi) {
    asm("mov.b64 {%0, %1}, %2;" : "=f"(lo), "=f"(hi) : "l"(v));
}
__device__ __forceinline__ ull fma2(ull a, ull b, ull c) {
    ull d; asm("fma.rn.f32x2 %0, %1, %2, %3;" : "=l"(d) : "l"(a), "l"(b), "l"(c));
    return d;
}
__device__ __forceinline__ ull ld64(const float2* p) {
    return *reinterpret_cast<const ull*>(p);
}

// ---------------------------------------------------------------------------
// LeNet feature kernel: one block per image
// ---------------------------------------------------------------------------
__global__ __launch_bounds__(BDIM, 3)
void lenet_kernel(const float* __restrict__ img,
                  const float* __restrict__ train,
                  const int*   __restrict__ refs,
                  const float* __restrict__ w1, const float* __restrict__ b1,
                  const float* __restrict__ w2, const float* __restrict__ b2,
                  const float* __restrict__ Wf, const float* __restrict__ bf,
                  int n_img)
{
    __shared__ float  s_img[3][32][32];       // 3072
    __shared__ float2 s_wp1[3][25][3];        // (oc2j, oc2j+1) pairs, 450 f
    __shared__ float2 s_wp2[6][25][8];        // 2400 f
    __shared__ float  s_b1[6];
    __shared__ float  s_b2[16];
    __shared__ float  s_p1[6][14][14];        // 1176
    __shared__ float  s_feat[FEAT];           // 400

    const int b = blockIdx.x;
    const int t = threadIdx.x;

    const float* src = (b < n_img)
        ? img + (size_t)b * 3072
        : train + (size_t)refs[b - n_img] * 3072;

    // load image: 768 float4
    {
        const float4* s4 = reinterpret_cast<const float4*>(src);
        float4* d4 = reinterpret_cast<float4*>(&s_img[0][0][0]);
        for (int i = t; i < 768; i += BDIM) d4[i] = s4[i];
    }
    // load packed weight pairs
    for (int i = t; i < 225; i += BDIM) {                // wp1: ic,k,j
        int ic = i / 75, r = i % 75, k = r / 3, j = r % 3;
        s_wp1[ic][k][j] = make_float2(w1[(2*j)     * 75 + ic * 25 + k],
                                      w1[(2*j + 1) * 75 + ic * 25 + k]);
    }
    for (int i = t; i < 1200; i += BDIM) {               // wp2: ic,k,j
        int ic = i / 200, r = i % 200, k = r / 8, j = r % 8;
        s_wp2[ic][k][j] = make_float2(w2[(2*j)     * 150 + ic * 25 + k],
                                      w2[(2*j + 1) * 150 + ic * 25 + k]);
    }
    if (t < 6)  s_b1[t] = b1[t];
    if (t < 16) s_b2[t] = b2[t];
    __syncthreads();

    // ---- conv1 + relu + maxpool2 : 6 x 14 x 14, FFMA2 over oc-pairs ----
    if (t < 196) {
        const int py = t / 14, px = t % 14;
        const int iy = 2 * py, ix = 2 * px;

        ull acc[3][4];
        #pragma unroll
        for (int j = 0; j < 3; j++) {
            ull bz = pack2(s_b1[2*j], s_b1[2*j + 1]);
            acc[j][0] = bz; acc[j][1] = bz; acc[j][2] = bz; acc[j][3] = bz;
        }
        #pragma unroll
        for (int ic = 0; ic < 3; ic++) {
            float in[6][6];
            #pragma unroll
            for (int r = 0; r < 6; r++)
                #pragma unroll
                for (int c = 0; c < 6; c++)
                    in[r][c] = s_img[ic][iy + r][ix + c];

            #pragma unroll
            for (int ky = 0; ky < 5; ky++) {
                #pragma unroll
                for (int kx = 0; kx < 5; kx++) {
                    const int k = ky * 5 + kx;
                    ull w0 = ld64(&s_wp1[ic][k][0]);
                    ull w1v = ld64(&s_wp1[ic][k][1]);
                    ull w2v = ld64(&s_wp1[ic][k][2]);

                    ull p = pack2(in[ky][kx], in[ky][kx]);
                    acc[0][0] = fma2(w0, p, acc[0][0]);
                    acc[1][0] = fma2(w1v, p, acc[1][0]);
                    acc[2][0] = fma2(w2v, p, acc[2][0]);

                    p = pack2(in[ky][kx+1], in[ky][kx+1]);
                    acc[0][1] = fma2(w0, p, acc[0][1]);
                    acc[1][1] = fma2(w1v, p, acc[1][1]);
                    acc[2][1] = fma2(w2v, p, acc[2][1]);

                    p = pack2(in[ky+1][kx], in[ky+1][kx]);
                    acc[0][2] = fma2(w0, p, acc[0][2]);
                    acc[1][2] = fma2(w1v, p, acc[1][2]);
                    acc[2][2] = fma2(w2v, p, acc[2][2]);

                    p = pack2(in[ky+1][kx+1], in[ky+1][kx+1]);
                    acc[0][3] = fma2(w0, p, acc[0][3]);
                    acc[1][3] = fma2(w1v, p, acc[1][3]);
                    acc[2][3] = fma2(w2v, p, acc[2][3]);
                }
            }
        }
        #pragma unroll
        for (int j = 0; j < 3; j++) {
            float a0l, a0h, a1l, a1h, a2l, a2h, a3l, a3h;
            unpack2(acc[j][0], a0l, a0h);
            unpack2(acc[j][1], a1l, a1h);
            unpack2(acc[j][2], a2l, a2h);
            unpack2(acc[j][3], a3l, a3h);
            float ml = fmaxf(fmaxf(a0l, a1l), fmaxf(a2l, a3l));
            float mh = fmaxf(fmaxf(a0h, a1h), fmaxf(a2h, a3h));
            s_p1[2*j    ][py][px] = fmaxf(ml, 0.0f);
            s_p1[2*j + 1][py][px] = fmaxf(mh, 0.0f);
        }
    }
    __syncthreads();

    // ---- conv2 + relu + maxpool2 : 16 x 5 x 5, (pos, oc-pair) tasks ----
    if (t < 200) {
        const int pos = t >> 3;        // 0..24
        const int j   = t & 7;         // oc pair 0..7
        const int py = pos / 5, px = pos % 5;
        const int iy = 2 * py, ix = 2 * px;

        ull a0, a1, a2, a3;
        {
            ull bz = pack2(s_b2[2*j], s_b2[2*j + 1]);
            a0 = bz; a1 = bz; a2 = bz; a3 = bz;
        }
        #pragma unroll
        for (int ic = 0; ic < 6; ic++) {
            float in[6][6];
            #pragma unroll
            for (int r = 0; r < 6; r++)
                #pragma unroll
                for (int c = 0; c < 6; c++)
                    in[r][c] = s_p1[ic][iy + r][ix + c];

            #pragma unroll
            for (int ky = 0; ky < 5; ky++) {
                #pragma unroll
                for (int kx = 0; kx < 5; kx++) {
                    ull w = ld64(&s_wp2[ic][ky * 5 + kx][j]);
                    a0 = fma2(w, pack2(in[ky  ][kx  ], in[ky  ][kx  ]), a0);
                    a1 = fma2(w, pack2(in[ky  ][kx+1], in[ky  ][kx+1]), a1);
                    a2 = fma2(w, pack2(in[ky+1][kx  ], in[ky+1][kx  ]), a2);
                    a3 = fma2(w, pack2(in[ky+1][kx+1], in[ky+1][kx+1]), a3);
                }
            }
        }
        float a0l,a0h,a1l,a1h,a2l,a2h,a3l,a3h;
        unpack2(a0, a0l, a0h); unpack2(a1, a1l, a1h);
        unpack2(a2, a2l, a2h); unpack2(a3, a3l, a3h);
        float ml = fmaxf(fmaxf(a0l, a1l), fmaxf(a2l, a3l));
        float mh = fmaxf(fmaxf(a0h, a1h), fmaxf(a2h, a3h));
        s_feat[(2*j    ) * 25 + pos] = fmaxf(ml, 0.0f);
        s_feat[(2*j + 1) * 25 + pos] = fmaxf(mh, 0.0f);
    }
    __syncthreads();

    if (b < n_img) {
        // query: store full feature vector
        float4* dst = reinterpret_cast<float4*>(g_feat + (size_t)b * FEAT);
        const float4* s4 = reinterpret_cast<const float4*>(s_feat);
        for (int i = t; i < 100; i += BDIM) dst[i] = s4[i];
    } else {
        // ref: project with Wf (12 warp-dots), store 12 floats only
        const int slot = b - n_img;
        const int warp = t >> 5, lane = t & 31;
        const float4* f4 = reinterpret_cast<const float4*>(s_feat);
        for (int d = warp; d < HID; d += (BDIM >> 5)) {
            const float4* w4 = reinterpret_cast<const float4*>(Wf + (size_t)d * FEAT);
            float acc = 0.0f;
            #pragma unroll
            for (int it = 0; it < 4; it++) {
                int e = lane + it * 32;
                if (e < 100) {
                    float4 a = f4[e], w = w4[e];
                    acc += a.x*w.x + a.y*w.y + a.z*w.z + a.w*w.w;
                }
            }
            #pragma unroll
            for (int o = 16; o > 0; o >>= 1)
                acc += __shfl_xor_sync(0xFFFFFFFFu, acc, o);
            if (lane == 0) g_rx[(size_t)slot * HID + d] = acc + bf[d];
        }
    }
}

// ---------------------------------------------------------------------------
// Head kernel: QPB queries per block, 256 threads (8 warps)
// ---------------------------------------------------------------------------
__global__ __launch_bounds__(256)
void head_kernel(const float* __restrict__ mem,
                 const int*   __restrict__ refs,
                 const float* __restrict__ Wf, const float* __restrict__ bf,
                 const float* __restrict__ Wg, const float* __restrict__ bg,
                 const float* __restrict__ Wm, const float* __restrict__ bm,
                 float* __restrict__ out, int n, int S)
{
    __shared__ float s_feat[QPB][FEAT];
    __shared__ float s_g[QPB][HID * NCLS];
    __shared__ float s_x[QPB][HID];
    __shared__ float s_rx[QPB][SMAX][HID];
    __shared__ float s_diff[QPB][SMAX][HID];
    __shared__ float s_norm[QPB][SMAX];
    __shared__ float s_mem[QPB][SMAX][NCLS];
    __shared__ float s_logit[QPB][SMAX][NCLS];
    __shared__ float s_wm[NCLS * NCLS];
    __shared__ float s_bm[NCLS];

    const int t = threadIdx.x;
    const int q0 = blockIdx.x * QPB;
    const int warp = t >> 5, lane = t & 31;

    // loads
    for (int i = t; i < QPB * 100; i += 256) {
        int ql = i / 100, e = i % 100;
        reinterpret_cast<float4*>(s_feat[ql])[e] =
            reinterpret_cast<const float4*>(g_feat + (size_t)(q0 + ql) * FEAT)[e];
    }
    for (int i = t; i < QPB * SMAX * NCLS; i += 256) {      // mem[refs]
        int ql = i / (SMAX * NCLS), r2 = i % (SMAX * NCLS);
        int s = r2 / NCLS, c = r2 % NCLS;
        int r = refs[(size_t)(q0 + ql) * S + s];
        s_mem[ql][s][c] = mem[(size_t)r * NCLS + c];
    }
    for (int i = t; i < QPB * SMAX * HID; i += 256) {       // ref projections
        int ql = i / (SMAX * HID), r2 = i % (SMAX * HID);
        int s = r2 / HID, h = r2 % HID;
        s_rx[ql][s][h] = g_rx[(size_t)((q0 + ql) * S + s) * HID + h];
    }
    if (t < NCLS * NCLS) s_wm[t] = Wm[t];
    if (t < NCLS) s_bm[t] = bm[t];
    __syncthreads();

    // 132 dot products (120 grad rows + 12 x rows), each for all QPB queries
    for (int d = warp; d < HID * NCLS + HID; d += 8) {
        const float* wrow; float bias;
        if (d < HID * NCLS) { wrow = Wg + (size_t)d * FEAT; bias = bg[d]; }
        else                { wrow = Wf + (size_t)(d - HID*NCLS) * FEAT; bias = bf[d - HID*NCLS]; }
        const float4* w4 = reinterpret_cast<const float4*>(wrow);
        float a[QPB] = {0.f, 0.f, 0.f, 0.f};
        #pragma unroll
        for (int it = 0; it < 4; it++) {
            int e = lane + it * 32;
            if (e < 100) {
                float4 w = w4[e];
                #pragma unroll
                for (int ql = 0; ql < QPB; ql++) {
                    float4 f = reinterpret_cast<const float4*>(s_feat[ql])[e];
                    a[ql] += f.x*w.x + f.y*w.y + f.z*w.z + f.w*w.w;
                }
            }
        }
        #pragma unroll
        for (int ql = 0; ql < QPB; ql++) {
            #pragma unroll
            for (int o = 16; o > 0; o >>= 1)
                a[ql] += __shfl_xor_sync(0xFFFFFFFFu, a[ql], o);
        }
        if (lane == 0) {
            #pragma unroll
            for (int ql = 0; ql < QPB; ql++) {
                float v = a[ql] + bias;
                if (d < HID * NCLS) s_g[ql][d] = v;
                else                s_x[ql][d - HID*NCLS] = v;
            }
        }
    }
    __syncthreads();

    // diff + norm
    if (t < QPB * SMAX) {
        int ql = t / SMAX, s = t % SMAX;
        float acc = 0.0f;
        #pragma unroll
        for (int h = 0; h < HID; h++) {
            float dd = s_x[ql][h] - s_rx[ql][s][h];
            s_diff[ql][s][h] = dd;
            acc += dd * dd;
        }
        s_norm[ql][s] = sqrtf(acc);
    }
    __syncthreads();

    // logits
    for (int i = t; i < QPB * SMAX * NCLS; i += 256) {
        int ql = i / (SMAX * NCLS), r2 = i % (SMAX * NCLS);
        int s = r2 / NCLS, c = r2 % NCLS;
        float acc = s_bm[c];
        #pragma unroll
        for (int jj = 0; jj < NCLS; jj++)
            acc += s_wm[c * NCLS + jj] * s_mem[ql][s][jj];
        #pragma unroll
        for (int h = 0; h < HID; h++)
            acc += s_diff[ql][s][h] * s_g[ql][h * NCLS + c];
        s_logit[ql][s][c] = acc;
    }
    __syncthreads();

    // softmax(-norm) weighted combine
    if (t < QPB * NCLS) {
        int ql = t / NCLS, c = t % NCLS;
        float mx = -1e30f;
        for (int s = 0; s < S; s++) mx = fmaxf(mx, -s_norm[ql][s]);
        float se = 0.0f, acc = 0.0f;
        for (int s = 0; s < S; s++) {
            float e = expf(-s_norm[ql][s] - mx);
            se += e;
            acc += e * s_logit[ql][s][c];
        }
        out[(size_t)(q0 + ql) * NCLS + c] = acc / se;
    }
}

// ---------------------------------------------------------------------------
// launcher
// ---------------------------------------------------------------------------
extern "C" void kernel_launch(void* const* d_in, const int* in_sizes, int n_in,
                              void* d_out, int out_size)
{
    const float* img   = (const float*)d_in[0];
    const float* train = (const float*)d_in[1];
    const float* mem   = (const float*)d_in[2];
    const float* w1    = (const float*)d_in[3];
    const float* b1    = (const float*)d_in[4];
    const float* w2    = (const float*)d_in[5];
    const float* b2    = (const float*)d_in[6];
    const float* Wf    = (const float*)d_in[7];
    const float* bf    = (const float*)d_in[8];
    const float* Wg    = (const float*)d_in[9];
    const float* bg    = (const float*)d_in[10];
    const float* Wm    = (const float*)d_in[11];
    const float* bm    = (const float*)d_in[12];
    // d_in[13] = idx : unused by the reference computation
    const int*   refs  = (const int*)d_in[14];

    const int n = in_sizes[0] / (3 * 32 * 32);   // 1024
    const int S = in_sizes[14] / n;              // 8
    if (n > NQ_MAX || S != SMAX || (n % QPB) != 0) return;

    const int ntot = n + n * S;                  // 9216
    lenet_kernel<<<ntot, BDIM>>>(img, train, refs, w1, b1, w2, b2, Wf, bf, n);
    head_kernel<<<n / QPB, 256>>>(mem, refs, Wf, bf, Wg, bg, Wm, bm,
                                  (float*)d_out, n, S);
}